// round 4
// baseline (speedup 1.0000x reference)
#include <cuda_runtime.h>

// SEIR scan, fused producer/consumer persistent kernel.
// Output layout: [4, T, B] — planes S, E, I, R.
//
// Producer warps (warps 14-15 of blocks 0..B/64-1): serial scan over T,
//   publishing chunk-boundary states every STEP steps + release counters.
// Consumer warps (everyone else, then producers after finishing): work-steal
//   (chunk, 128-channel-group) tasks, wait for the chunk boundary, recompute
//   STEP rows, stream them out with float4 evict-first stores.

#define STEP   16
#define RING   32
#define MAXB   8192
#define MAXC   256      // supports T up to 4096

__device__ float g_bS[MAXC * MAXB];
__device__ float g_bE[MAXC * MAXB];
__device__ float g_bI[MAXC * MAXB];
__device__ float g_bR[MAXC * MAXB];
__device__ unsigned g_sync[MAXC + 1];   // [0..MAXC): done counters, [MAXC]: task ctr

__device__ __forceinline__ unsigned ld_acq(const unsigned* p)
{
    unsigned v;
    asm volatile("ld.acquire.gpu.global.u32 %0, [%1];"
                 : "=r"(v) : "l"(p) : "memory");
    return v;
}

// one SEIR step; invN folded into wbN
__device__ __forceinline__ void seir_step(float x, float wbN, float wg, float ws,
                                          float& S, float& E, float& I, float& R)
{
    const float t1   = x * wbN;
    const float t2   = x * ws;
    const float t3   = x * wg;
    const float StoE = t1 * I * S;
    const float EtoI = t2 * E;
    const float ItoR = t3 * I;
    S = S - StoE;
    E = E + (StoE - EtoI);
    I = I + (EtoI - ItoR);
    R = R + ItoR;
}

template<int B_>
__global__ __launch_bounds__(512, 2)
void seir_fused(const float* __restrict__ X,
                const float* __restrict__ w_beta,
                const float* __restrict__ w_gamma,
                const float* __restrict__ w_sigma,
                const float* __restrict__ S0,
                const float* __restrict__ I0,
                const float* __restrict__ R0,
                const float* __restrict__ Nvec,
                float* __restrict__ out,
                int T, int chunks, int totalTasks)
{
    const int tid  = threadIdx.x;
    const int lane = tid & 31;

    // ---------------------------------------------------------- producer
    if (blockIdx.x < (B_ / 64) && tid >= 448) {
        const int b = blockIdx.x * 64 + (tid - 448);

        const float invN = 1.0f / Nvec[b];
        const float wbN  = w_beta[b] * invN;
        const float wg   = w_gamma[b];
        const float ws   = w_sigma[b];

        float S = S0[b];
        float E = 0.0f;
        float I = I0[b];
        float R = R0[b];

        const int NS = (chunks - 1) * STEP;
        const float* __restrict__ xp = X + b;

        float xr[RING];
#pragma unroll
        for (int k = 0; k < RING; ++k)
            xr[k] = (k < NS) ? xp[(size_t)k * B_] : 0.0f;

        int base = 0;
        for (; base + 2 * RING <= NS; base += RING) {
            const float* __restrict__ pf = xp + (size_t)(base + RING) * B_;
#pragma unroll
            for (int k = 0; k < RING; ++k) {
                const float x = xr[k];
                xr[k] = pf[(size_t)k * B_];          // immediate offsets (B_ const)
                seir_step(x, wbN, wg, ws, S, E, I, R);
                if (((k + 1) & (STEP - 1)) == 0) {   // static: k = 15, 31
                    const int c   = (base + k + 1) / STEP;
                    const int idx = c * B_ + b;
                    g_bS[idx] = S; g_bE[idx] = E; g_bI[idx] = I; g_bR[idx] = R;
                    __syncwarp();
                    __threadfence();
                    if (lane == 0) atomicAdd(&g_sync[c], 32u);
                }
            }
        }
        // tail: at most 2*RING predicated steps
#pragma unroll
        for (int k = 0; k < RING; ++k) {
            const int t = base + k;
            if (t < NS) {
                const float x = xr[k];
                const int tn = t + RING;
                xr[k] = (tn < NS) ? xp[(size_t)tn * B_] : 0.0f;
                seir_step(x, wbN, wg, ws, S, E, I, R);
                if (((t + 1) & (STEP - 1)) == 0) {
                    const int c   = (t + 1) / STEP;
                    const int idx = c * B_ + b;
                    g_bS[idx] = S; g_bE[idx] = E; g_bI[idx] = I; g_bR[idx] = R;
                    __syncwarp();
                    __threadfence();
                    if (lane == 0) atomicAdd(&g_sync[c], 32u);
                }
            }
        }
        base += RING;
#pragma unroll
        for (int k = 0; k < RING; ++k) {
            const int t = base + k;
            if (t < NS) {
                const float x = xr[k];
                seir_step(x, wbN, wg, ws, S, E, I, R);
                if (((t + 1) & (STEP - 1)) == 0) {
                    const int c   = (t + 1) / STEP;
                    const int idx = c * B_ + b;
                    g_bS[idx] = S; g_bE[idx] = E; g_bI[idx] = I; g_bR[idx] = R;
                    __syncwarp();
                    __threadfence();
                    if (lane == 0) atomicAdd(&g_sync[c], 32u);
                }
            }
        }
        // fall through: producer warps join the consumer pool
    }

    // ---------------------------------------------------------- consumers
    constexpr int GROUPS = B_ / 128;   // warp-tasks per chunk

    const size_t TB = (size_t)T * (size_t)B_;
    float* __restrict__ oS = out;
    float* __restrict__ oE = out + TB;
    float* __restrict__ oI = out + 2 * TB;
    float* __restrict__ oR = out + 3 * TB;

    for (;;) {
        unsigned id;
        if (lane == 0) id = atomicAdd(&g_sync[MAXC], 1u);
        id = __shfl_sync(0xffffffffu, id, 0);
        if (id >= (unsigned)totalTasks) break;

        const int c = (int)(id / GROUPS);
        const int g = (int)(id % GROUPS);
        const int b = g * 128 + lane * 4;

        const int t0  = c * STEP;
        const int nst = min(STEP, T - t0) - 1;

        const float4 wb = *(const float4*)(w_beta  + b);
        const float4 wg = *(const float4*)(w_gamma + b);
        const float4 ws = *(const float4*)(w_sigma + b);
        const float4 nv = *(const float4*)(Nvec    + b);
        const float4 wbN = make_float4(wb.x / nv.x, wb.y / nv.y,
                                       wb.z / nv.z, wb.w / nv.w);

        float4 S, E, I, R;
        if (c == 0) {
            S = *(const float4*)(S0 + b);
            E = make_float4(0.f, 0.f, 0.f, 0.f);
            I = *(const float4*)(I0 + b);
            R = *(const float4*)(R0 + b);
        } else {
            while (ld_acq(&g_sync[c]) < (unsigned)B_)
                __nanosleep(64);
            const int bi = c * B_ + b;
            S = *(const float4*)(g_bS + bi);
            E = *(const float4*)(g_bE + bi);
            I = *(const float4*)(g_bI + bi);
            R = *(const float4*)(g_bR + bi);
        }

        size_t r = (size_t)t0 * B_ + b;
        __stcs((float4*)(oS + r), S);
        __stcs((float4*)(oE + r), E);
        __stcs((float4*)(oI + r), I);
        __stcs((float4*)(oR + r), R);

        const float* __restrict__ xp = X + (size_t)t0 * B_ + b;
        float4 xn = (nst > 0) ? *(const float4*)xp
                              : make_float4(0.f, 0.f, 0.f, 0.f);

        if (nst == STEP - 1) {
#pragma unroll
            for (int i = 0; i < STEP - 1; ++i) {
                const float4 x = xn;
                if (i + 1 < STEP - 1)
                    xn = *(const float4*)(xp + (size_t)(i + 1) * B_);
                seir_step(x.x, wbN.x, wg.x, ws.x, S.x, E.x, I.x, R.x);
                seir_step(x.y, wbN.y, wg.y, ws.y, S.y, E.y, I.y, R.y);
                seir_step(x.z, wbN.z, wg.z, ws.z, S.z, E.z, I.z, R.z);
                seir_step(x.w, wbN.w, wg.w, ws.w, S.w, E.w, I.w, R.w);
                r += B_;
                __stcs((float4*)(oS + r), S);
                __stcs((float4*)(oE + r), E);
                __stcs((float4*)(oI + r), I);
                __stcs((float4*)(oR + r), R);
            }
        } else {
            for (int i = 0; i < nst; ++i) {
                const float4 x = xn;
                if (i + 1 < nst)
                    xn = *(const float4*)(xp + (size_t)(i + 1) * B_);
                seir_step(x.x, wbN.x, wg.x, ws.x, S.x, E.x, I.x, R.x);
                seir_step(x.y, wbN.y, wg.y, ws.y, S.y, E.y, I.y, R.y);
                seir_step(x.z, wbN.z, wg.z, ws.z, S.z, E.z, I.z, R.z);
                seir_step(x.w, wbN.w, wg.w, ws.w, S.w, E.w, I.w, R.w);
                r += B_;
                __stcs((float4*)(oS + r), S);
                __stcs((float4*)(oE + r), E);
                __stcs((float4*)(oI + r), I);
                __stcs((float4*)(oR + r), R);
            }
        }
    }
}

// ------------------------------------------------ fallback (shape safety)
__global__ void seir_fallback(const float* __restrict__ X,
                              const float* __restrict__ w_beta,
                              const float* __restrict__ w_gamma,
                              const float* __restrict__ w_sigma,
                              const float* __restrict__ S0,
                              const float* __restrict__ I0,
                              const float* __restrict__ R0,
                              const float* __restrict__ Nvec,
                              float* __restrict__ out, int T, int B)
{
    const int b = blockIdx.x * blockDim.x + threadIdx.x;
    if (b >= B) return;
    const float invN = 1.0f / Nvec[b];
    const float wbN = w_beta[b] * invN;
    const float wg = w_gamma[b], ws = w_sigma[b];
    float S = S0[b], E = 0.0f, I = I0[b], R = R0[b];
    const size_t TB = (size_t)T * B;
    out[b] = S; out[TB + b] = E; out[2 * TB + b] = I; out[3 * TB + b] = R;
    for (int t = 0; t < T - 1; ++t) {
        const float x = X[(size_t)t * B + b];
        seir_step(x, wbN, wg, ws, S, E, I, R);
        const size_t r = (size_t)(t + 1) * B + b;
        out[r] = S; out[TB + r] = E; out[2 * TB + r] = I; out[3 * TB + r] = R;
    }
}

extern "C" void kernel_launch(void* const* d_in, const int* in_sizes, int n_in,
                              void* d_out, int out_size)
{
    const float* X      = (const float*)d_in[0];
    const float* w_beta = (const float*)d_in[1];
    const float* w_gamma= (const float*)d_in[2];
    const float* w_sigma= (const float*)d_in[3];
    const float* S0     = (const float*)d_in[4];
    const float* I0     = (const float*)d_in[5];
    const float* R0     = (const float*)d_in[6];
    const float* Nvec   = (const float*)d_in[7];
    float* out = (float*)d_out;

    const int B = in_sizes[1];         // w_beta is [B]
    const int T = in_sizes[0] / B;     // X is [T, B]
    const int chunks = (T + STEP - 1) / STEP;

    if (B == 8192 && chunks <= MAXC && T >= 2) {
        void* sync_addr = nullptr;
        cudaGetSymbolAddress(&sync_addr, g_sync);
        cudaMemsetAsync(sync_addr, 0, sizeof(unsigned) * (MAXC + 1), 0);

        const int totalTasks = chunks * (B / 128);
        seir_fused<8192><<<304, 512>>>(X, w_beta, w_gamma, w_sigma,
                                       S0, I0, R0, Nvec, out,
                                       T, chunks, totalTasks);
    } else {
        seir_fallback<<<(B + 127) / 128, 128>>>(X, w_beta, w_gamma, w_sigma,
                                                S0, I0, R0, Nvec, out, T, B);
    }
}

// round 6
// speedup vs baseline: 4.8050x; 4.8050x over previous
#include <cuda_runtime.h>

// SEIR scan — single persistent kernel, producer/consumer software pipeline
// synchronized by a grid-wide sense-reversing barrier (8 barriers total).
// Output layout: [4, T, B] — planes S, E, I, R.
//
// Producer warps (warps 14-15 of blocks 0..127): persistent serial scan,
//   one SEG=256-step segment per round, boundary states every STEP=16 steps.
// Consumer warps (all others): in round r, statically-assigned tasks
//   (chunk, 128-channel group) of segment r-1; float4 evict-first stores.

#define STEP   16
#define CPS    16
#define SEG    (STEP * CPS)     // 256 steps per segment
#define RING   32
#define MAXB   8192
#define MAXC   260              // supports T up to ~4096
#define NBLOCKS  148
#define NTHREADS 512

__device__ float g_bS[MAXC * MAXB];
__device__ float g_bE[MAXC * MAXB];
__device__ float g_bI[MAXC * MAXB];
__device__ float g_bR[MAXC * MAXB];

__device__ unsigned g_count = 0;   // barrier arrivals (returns to 0 each barrier)
__device__ unsigned g_epoch = 0;   // barrier epoch (monotonic across replays)

__device__ __forceinline__ void grid_barrier()
{
    __syncthreads();
    if (threadIdx.x == 0) {
        __threadfence();
        unsigned e;
        asm volatile("ld.acquire.gpu.global.u32 %0, [%1];"
                     : "=r"(e) : "l"(&g_epoch) : "memory");
        const unsigned a = atomicAdd(&g_count, 1);
        if (a == NBLOCKS - 1) {
            g_count = 0;  // ordered before the release-store below
            asm volatile("st.release.gpu.global.u32 [%0], %1;"
                         :: "l"(&g_epoch), "r"(e + 1) : "memory");
        } else {
            unsigned cur;
            do {
                __nanosleep(64);
                asm volatile("ld.acquire.gpu.global.u32 %0, [%1];"
                             : "=r"(cur) : "l"(&g_epoch) : "memory");
            } while (cur == e);
        }
    }
    __syncthreads();
}

// one SEIR step, fma form; invN folded into wbN.
__device__ __forceinline__ void seir_step2(float x, float wbN, float wg, float ws,
                                           float& S, float& E, float& I, float& R)
{
    const float bN = x * wbN;
    const float s2 = x * ws;
    const float g3 = x * wg;
    const float eD = 1.0f - s2;
    const float iD = 1.0f - g3;
    const float v    = bN * I;
    const float StoE = v * S;
    const float EtoI = s2 * E;
    const float Sn = fmaf(-v, S, S);
    const float En = fmaf(E, eD, StoE);
    const float In = fmaf(I, iD, EtoI);
    const float Rn = fmaf(g3, I, R);
    S = Sn; E = En; I = In; R = Rn;
}

template<int B_>
__global__ __launch_bounds__(NTHREADS, 1)
void seir_pipe(const float* __restrict__ X,
               const float* __restrict__ w_beta,
               const float* __restrict__ w_gamma,
               const float* __restrict__ w_sigma,
               const float* __restrict__ S0,
               const float* __restrict__ I0,
               const float* __restrict__ R0,
               const float* __restrict__ Nvec,
               float* __restrict__ out,
               int T, int chunks, int nseg)
{
    const int tid  = threadIdx.x;
    const int wid  = tid >> 5;
    const int lane = tid & 31;

    constexpr int PRODBLOCKS = B_ / 64;        // 128
    constexpr int GROUPS     = B_ / 128;       // 64 tasks per chunk

    const bool is_prod = (blockIdx.x < PRODBLOCKS) && (wid >= 14);

    // consumer warp linear id (valid only when !is_prod)
    int cw;
    if (blockIdx.x < PRODBLOCKS)
        cw = blockIdx.x * 14 + wid;                        // 0 .. 1791
    else
        cw = PRODBLOCKS * 14 + (blockIdx.x - PRODBLOCKS) * 16 + wid;

    // ---- producer persistent state ----
    float S = 0.f, E = 0.f, I = 0.f, R = 0.f;
    float p_wbN = 0.f, p_wg = 0.f, p_ws = 0.f;
    int   pb = 0;
    if (is_prod) {
        pb = blockIdx.x * 64 + (wid - 14) * 32 + lane;
        const float invN = 1.0f / Nvec[pb];
        p_wbN = w_beta[pb] * invN;
        p_wg  = w_gamma[pb];
        p_ws  = w_sigma[pb];
        S = S0[pb]; E = 0.0f; I = I0[pb]; R = R0[pb];
        // boundary 0 = initial state
        g_bS[pb] = S; g_bE[pb] = E; g_bI[pb] = I; g_bR[pb] = R;
    }

    const int NS_total = (chunks - 1) * STEP;

    const size_t TB = (size_t)T * (size_t)B_;
    float* __restrict__ oS = out;
    float* __restrict__ oE = out + TB;
    float* __restrict__ oI = out + 2 * TB;
    float* __restrict__ oR = out + 3 * TB;

    for (int r = 0; r <= nseg; ++r) {

        // -------------------------------------------------- producer: seg r
        if (is_prod && r < nseg) {
            const int t0 = r * SEG;
            const int ns = min(SEG, NS_total - t0);
            if (ns > 0) {
                const float* __restrict__ xp = X + (size_t)t0 * B_ + pb;
                float xr[RING];
#pragma unroll
                for (int k = 0; k < RING; ++k)
                    xr[k] = (k < ns) ? xp[(size_t)k * B_] : 0.0f;

                int base = 0;
                for (; base + 2 * RING <= ns; base += RING) {
                    const float* __restrict__ pf = xp + (size_t)(base + RING) * B_;
#pragma unroll
                    for (int k = 0; k < RING; ++k) {
                        const float x = xr[k];
                        xr[k] = pf[(size_t)k * B_];
                        seir_step2(x, p_wbN, p_wg, p_ws, S, E, I, R);
                        if (((k + 1) & (STEP - 1)) == 0) {
                            const int c   = r * CPS + (base + k + 1) / STEP;
                            const int idx = c * B_ + pb;
                            g_bS[idx] = S; g_bE[idx] = E;
                            g_bI[idx] = I; g_bR[idx] = R;
                        }
                    }
                }
                // drain (no prefetch), predicated for partial segments
                for (; base < ns; base += RING) {
#pragma unroll
                    for (int k = 0; k < RING; ++k) {
                        const int t = base + k;
                        if (t < ns) {
                            const float x = xr[k];
                            seir_step2(x, p_wbN, p_wg, p_ws, S, E, I, R);
                            if (((t + 1) & (STEP - 1)) == 0) {
                                const int c   = r * CPS + (t + 1) / STEP;
                                const int idx = c * B_ + pb;
                                g_bS[idx] = S; g_bE[idx] = E;
                                g_bI[idx] = I; g_bR[idx] = R;
                            }
                        }
                    }
                }
            }
        }

        // ---------------------------------------------- consumer: seg r-1
        if (!is_prod && r >= 1) {
            const int cbase  = (r - 1) * CPS;
            const int nch    = min(CPS, chunks - cbase);
            const int ntasks = nch * GROUPS;
            if (cw < ntasks) {
                const int c = cbase + cw / GROUPS;
                const int g = cw % GROUPS;
                const int b = g * 128 + lane * 4;

                const int t0  = c * STEP;
                const int nst = min(STEP, T - t0) - 1;

                const float4 wb = *(const float4*)(w_beta  + b);
                const float4 wg = *(const float4*)(w_gamma + b);
                const float4 ws = *(const float4*)(w_sigma + b);
                const float4 nv = *(const float4*)(Nvec    + b);
                const float4 wbN = make_float4(wb.x / nv.x, wb.y / nv.y,
                                               wb.z / nv.z, wb.w / nv.w);

                const int bi = c * B_ + b;
                float4 Sc = *(const float4*)(g_bS + bi);
                float4 Ec = *(const float4*)(g_bE + bi);
                float4 Ic = *(const float4*)(g_bI + bi);
                float4 Rc = *(const float4*)(g_bR + bi);

                size_t rr = (size_t)t0 * B_ + b;
                __stcs((float4*)(oS + rr), Sc);
                __stcs((float4*)(oE + rr), Ec);
                __stcs((float4*)(oI + rr), Ic);
                __stcs((float4*)(oR + rr), Rc);

                const float* __restrict__ xp = X + (size_t)t0 * B_ + b;
                float4 xn = (nst > 0) ? *(const float4*)xp
                                      : make_float4(0.f, 0.f, 0.f, 0.f);

                if (nst == STEP - 1) {
#pragma unroll
                    for (int i = 0; i < STEP - 1; ++i) {
                        const float4 x = xn;
                        if (i + 1 < STEP - 1)
                            xn = *(const float4*)(xp + (size_t)(i + 1) * B_);
                        seir_step2(x.x, wbN.x, wg.x, ws.x, Sc.x, Ec.x, Ic.x, Rc.x);
                        seir_step2(x.y, wbN.y, wg.y, ws.y, Sc.y, Ec.y, Ic.y, Rc.y);
                        seir_step2(x.z, wbN.z, wg.z, ws.z, Sc.z, Ec.z, Ic.z, Rc.z);
                        seir_step2(x.w, wbN.w, wg.w, ws.w, Sc.w, Ec.w, Ic.w, Rc.w);
                        rr += B_;
                        __stcs((float4*)(oS + rr), Sc);
                        __stcs((float4*)(oE + rr), Ec);
                        __stcs((float4*)(oI + rr), Ic);
                        __stcs((float4*)(oR + rr), Rc);
                    }
                } else {
                    for (int i = 0; i < nst; ++i) {
                        const float4 x = xn;
                        if (i + 1 < nst)
                            xn = *(const float4*)(xp + (size_t)(i + 1) * B_);
                        seir_step2(x.x, wbN.x, wg.x, ws.x, Sc.x, Ec.x, Ic.x, Rc.x);
                        seir_step2(x.y, wbN.y, wg.y, ws.y, Sc.y, Ec.y, Ic.y, Rc.y);
                        seir_step2(x.z, wbN.z, wg.z, ws.z, Sc.z, Ec.z, Ic.z, Rc.z);
                        seir_step2(x.w, wbN.w, wg.w, ws.w, Sc.w, Ec.w, Ic.w, Rc.w);
                        rr += B_;
                        __stcs((float4*)(oS + rr), Sc);
                        __stcs((float4*)(oE + rr), Ec);
                        __stcs((float4*)(oI + rr), Ic);
                        __stcs((float4*)(oR + rr), Rc);
                    }
                }
            }
        }

        if (r < nseg) grid_barrier();
    }
}

// ------------------------------------------------ fallback (shape safety)
__global__ void seir_fallback(const float* __restrict__ X,
                              const float* __restrict__ w_beta,
                              const float* __restrict__ w_gamma,
                              const float* __restrict__ w_sigma,
                              const float* __restrict__ S0,
                              const float* __restrict__ I0,
                              const float* __restrict__ R0,
                              const float* __restrict__ Nvec,
                              float* __restrict__ out, int T, int B)
{
    const int b = blockIdx.x * blockDim.x + threadIdx.x;
    if (b >= B) return;
    const float invN = 1.0f / Nvec[b];
    const float wbN = w_beta[b] * invN;
    const float wg = w_gamma[b], ws = w_sigma[b];
    float S = S0[b], E = 0.0f, I = I0[b], R = R0[b];
    const size_t TB = (size_t)T * B;
    out[b] = S; out[TB + b] = E; out[2 * TB + b] = I; out[3 * TB + b] = R;
    for (int t = 0; t < T - 1; ++t) {
        const float x = X[(size_t)t * B + b];
        seir_step2(x, wbN, wg, ws, S, E, I, R);
        const size_t r = (size_t)(t + 1) * B + b;
        out[r] = S; out[TB + r] = E; out[2 * TB + r] = I; out[3 * TB + r] = R;
    }
}

extern "C" void kernel_launch(void* const* d_in, const int* in_sizes, int n_in,
                              void* d_out, int out_size)
{
    const float* X      = (const float*)d_in[0];
    const float* w_beta = (const float*)d_in[1];
    const float* w_gamma= (const float*)d_in[2];
    const float* w_sigma= (const float*)d_in[3];
    const float* S0     = (const float*)d_in[4];
    const float* I0     = (const float*)d_in[5];
    const float* R0     = (const float*)d_in[6];
    const float* Nvec   = (const float*)d_in[7];
    float* out = (float*)d_out;

    const int B = in_sizes[1];         // w_beta is [B]
    const int T = in_sizes[0] / B;     // X is [T, B]
    const int chunks = (T + STEP - 1) / STEP;

    if (B == 8192 && chunks <= MAXC && T >= 2) {
        const int nseg = (chunks + CPS - 1) / CPS;
        seir_pipe<8192><<<NBLOCKS, NTHREADS>>>(X, w_beta, w_gamma, w_sigma,
                                               S0, I0, R0, Nvec, out,
                                               T, chunks, nseg);
    } else {
        seir_fallback<<<(B + 127) / 128, 128>>>(X, w_beta, w_gamma, w_sigma,
                                                S0, I0, R0, Nvec, out, T, B);
    }
}